// round 1
// baseline (speedup 1.0000x reference)
#include <cuda_runtime.h>
#include <math.h>

#define FFT_N      8192
#define FFT_LOGN   13
#define THREADS    512
#define BF_PER_T   (FFT_N / 2 / THREADS)   // 8 butterflies per thread per stage
#define PTS_PER_T  (FFT_N / THREADS)       // 16

// Stockham radix-2 DIF, natural order in/out, ping-pong between b0 and b1.
// After FFT_LOGN (=13, odd) stages the result lives in b1.
__device__ __forceinline__ void fft8192(float2* __restrict__ b0,
                                        float2* __restrict__ b1,
                                        int tid) {
    float2* src = b0;
    float2* dst = b1;
    int l = FFT_N / 2;      // 4096
    int sm = 0;             // log2(m), m = 1
    #pragma unroll 1
    for (int stage = 0; stage < FFT_LOGN; stage++) {
        const int m = 1 << sm;
        const float wstep = -(float)M_PI / (float)l;   // angle = wstep * j
        #pragma unroll
        for (int i = 0; i < BF_PER_T; i++) {
            const int t  = tid + i * THREADS;          // t = j*m + k, t in [0, N/2)
            const int j  = t >> sm;
            const float2 c0 = src[t];
            const float2 c1 = src[t + FFT_N / 2];
            float s, c;
            __sincosf(wstep * (float)j, &s, &c);
            const float sx = c0.x + c1.x, sy = c0.y + c1.y;
            const float dx = c0.x - c1.x, dy = c0.y - c1.y;
            const int d0 = t + (j << sm);
            dst[d0]     = make_float2(sx, sy);
            dst[d0 + m] = make_float2(dx * c - dy * s, dx * s + dy * c);
        }
        __syncthreads();
        float2* tmp = src; src = dst; dst = tmp;
        l >>= 1;
        sm++;
    }
}

__global__ void __launch_bounds__(THREADS, 1)
batch_align_kernel(const float* __restrict__ x,
                   const float* __restrict__ xref,
                   float* __restrict__ out_aligned,
                   float* __restrict__ out_inds) {
    const int row = blockIdx.x;
    const float* xr = x    + (size_t)row * FFT_N;
    const float* yr = xref + (size_t)row * FFT_N;

    extern __shared__ float smem_raw[];
    float2* b0   = (float2*)smem_raw;            // 64 KB
    float2* b1   = b0 + FFT_N;                   // 64 KB
    float*  redv = (float*)(b1 + FFT_N);         // 2 KB
    int*    redi = (int*)(redv + THREADS);       // 2 KB

    const int tid = threadIdx.x;

    // --- load z = x + i*xref ---
    #pragma unroll
    for (int i = 0; i < PTS_PER_T; i++) {
        const int k = tid + i * THREADS;
        b0[k] = make_float2(xr[k], yr[k]);
    }
    __syncthreads();

    // --- forward FFT of packed signal: Z in b1 ---
    fft8192(b0, b1, tid);

    // --- Hermitian split + V[k] = X[k] * conj(Y[k])  (= conj(W), W = conj(X)Y),
    //     up to a positive scale (argmax-invariant). Write V into b0. ---
    for (int k = tid; k <= FFT_N / 2; k += THREADS) {
        const float2 Zk = b1[k];
        const float2 Zn = b1[(FFT_N - k) & (FFT_N - 1)];
        // X' = Zk + conj(Zn)   (= 2X)
        const float Xr = Zk.x + Zn.x;
        const float Xi = Zk.y - Zn.y;
        // Y' = -i (Zk - conj(Zn))   (= 2Y)
        const float Yr = Zk.y + Zn.y;
        const float Yi = Zn.x - Zk.x;
        // V = X' * conj(Y')
        const float Vr = Xr * Yr + Xi * Yi;
        const float Vi = Xi * Yr - Xr * Yi;
        b0[k] = make_float2(Vr, Vi);
        if (k > 0 && k < FFT_N / 2)
            b0[FFT_N - k] = make_float2(Vr, -Vi);   // V[N-k] = conj(V[k])
    }
    __syncthreads();

    // --- second forward FFT: corr (unscaled) = Re(b1[n]) ---
    fft8192(b0, b1, tid);

    // --- argmax with first-index tiebreak (matches jnp.argmax) ---
    float best = -INFINITY;
    int   bidx = 0;
    #pragma unroll
    for (int i = 0; i < PTS_PER_T; i++) {
        const int k = tid + i * THREADS;   // increasing k per thread
        const float v = b1[k].x;
        if (v > best) { best = v; bidx = k; }
    }
    redv[tid] = best;
    redi[tid] = bidx;
    __syncthreads();
    #pragma unroll 1
    for (int s = THREADS / 2; s > 0; s >>= 1) {
        if (tid < s) {
            const float v2 = redv[tid + s];
            const int   i2 = redi[tid + s];
            if (v2 > redv[tid] || (v2 == redv[tid] && i2 < redi[tid])) {
                redv[tid] = v2;
                redi[tid] = i2;
            }
        }
        __syncthreads();
    }
    const int ind = redi[0];

    // --- circular roll: out[k] = x[(k - ind) mod N] ---
    #pragma unroll
    for (int i = 0; i < PTS_PER_T; i++) {
        const int k = tid + i * THREADS;
        out_aligned[(size_t)row * FFT_N + k] = xr[(k - ind) & (FFT_N - 1)];
    }
    if (tid == 0)
        out_inds[row] = (float)ind;
}

extern "C" void kernel_launch(void* const* d_in, const int* in_sizes, int n_in,
                              void* d_out, int out_size) {
    const float* x    = (const float*)d_in[0];
    const float* xref = (const float*)d_in[1];
    float* out = (float*)d_out;

    const int rows = in_sizes[0] / FFT_N;    // 32*64 = 2048
    float* out_aligned = out;
    float* out_inds    = out + (size_t)rows * FFT_N;

    const size_t smem = 2 * FFT_N * sizeof(float2)
                      + THREADS * (sizeof(float) + sizeof(int));
    cudaFuncSetAttribute(batch_align_kernel,
                         cudaFuncAttributeMaxDynamicSharedMemorySize, (int)smem);
    batch_align_kernel<<<rows, THREADS, smem>>>(x, xref, out_aligned, out_inds);
}

// round 4
// speedup vs baseline: 1.7547x; 1.7547x over previous
#include <cuda_runtime.h>
#include <math.h>

#define FFT_N      8192
#define THREADS    512
#define PTS_PER_T  (FFT_N / THREADS)       // 16
#define PAD(i)     ((i) + ((i) >> 4))      // pad 1 float2 per 16 -> breaks pow2 stride conflicts
#define PADN       (FFT_N + (FFT_N >> 4))  // 8704 float2

__device__ __forceinline__ float2 cadd(float2 a, float2 b) { return make_float2(a.x + b.x, a.y + b.y); }
__device__ __forceinline__ float2 csub(float2 a, float2 b) { return make_float2(a.x - b.x, a.y - b.y); }
__device__ __forceinline__ float2 cmul(float2 a, float2 b) {
    return make_float2(a.x * b.x - a.y * b.y, a.x * b.y + a.y * b.x);
}
// multiply by -i:  (x + iy)(-i) = y - ix
__device__ __forceinline__ float2 cmul_negi(float2 a) { return make_float2(a.y, -a.x); }

// Stockham DIF, radices [8,8,8,8,2]. Natural order in/out.
// src=b0 initially; result lands in b1 (5 stages, odd number of swaps).
__device__ __forceinline__ void fft8192_r8(float2* __restrict__ b0,
                                           float2* __restrict__ b1,
                                           int tid) {
    const float C = 0.70710678118654752f;   // sqrt(2)/2
    float2* src = b0;
    float2* dst = b1;

    #pragma unroll
    for (int s = 0; s < 4; s++) {
        const int sh = 3 * s;
        const int m  = 1 << sh;
        #pragma unroll
        for (int i = 0; i < 2; i++) {
            const int t = tid + i * THREADS;        // t in [0, 1024)
            const int j = t >> sh;
            const int k = t & (m - 1);

            float2 a0 = src[PAD(t + 0 * 1024)];
            float2 a1 = src[PAD(t + 1 * 1024)];
            float2 a2 = src[PAD(t + 2 * 1024)];
            float2 a3 = src[PAD(t + 3 * 1024)];
            float2 a4 = src[PAD(t + 4 * 1024)];
            float2 a5 = src[PAD(t + 5 * 1024)];
            float2 a6 = src[PAD(t + 6 * 1024)];
            float2 a7 = src[PAD(t + 7 * 1024)];

            // 8-point DFT (omega_8 = e^{-2*pi*i/8})
            float2 u0 = cadd(a0, a4), u1 = csub(a0, a4);
            float2 u2 = cadd(a2, a6), u3 = csub(a2, a6);
            float2 E0 = cadd(u0, u2), E2 = csub(u0, u2);
            float2 mi3 = cmul_negi(u3);
            float2 E1 = cadd(u1, mi3), E3 = csub(u1, mi3);

            float2 v0 = cadd(a1, a5), v1 = csub(a1, a5);
            float2 v2 = cadd(a3, a7), v3 = csub(a3, a7);
            float2 O0 = cadd(v0, v2), O2 = csub(v0, v2);
            float2 ni3 = cmul_negi(v3);
            float2 O1 = cadd(v1, ni3), O3 = csub(v1, ni3);

            // omega_8^1 O1, omega_8^2 O2, omega_8^3 O3
            float2 w1O = make_float2(C * (O1.x + O1.y), C * (O1.y - O1.x));
            float2 w2O = cmul_negi(O2);
            float2 w3O = make_float2(C * (O3.y - O3.x), -C * (O3.x + O3.y));

            float2 y0 = cadd(E0, O0),  y4 = csub(E0, O0);
            float2 y1 = cadd(E1, w1O), y5 = csub(E1, w1O);
            float2 y2 = cadd(E2, w2O), y6 = csub(E2, w2O);
            float2 y3 = cadd(E3, w3O), y7 = csub(E3, w3O);

            // stage twiddles: w^q', w = e^{-2*pi*i * j*m / 8192}
            float sn, cs;
            __sincosf(-(float)M_PI * (float)(j << sh) * (1.0f / 4096.0f), &sn, &cs);
            const float2 w1 = make_float2(cs, sn);
            const float2 w2 = cmul(w1, w1);
            const float2 w3 = cmul(w2, w1);
            const float2 w4 = cmul(w2, w2);
            const float2 w5 = cmul(w4, w1);
            const float2 w6 = cmul(w4, w2);
            const float2 w7 = cmul(w4, w3);

            const int base = (j << (sh + 3)) + k;
            dst[PAD(base + 0 * m)] = y0;
            dst[PAD(base + 1 * m)] = cmul(y1, w1);
            dst[PAD(base + 2 * m)] = cmul(y2, w2);
            dst[PAD(base + 3 * m)] = cmul(y3, w3);
            dst[PAD(base + 4 * m)] = cmul(y4, w4);
            dst[PAD(base + 5 * m)] = cmul(y5, w5);
            dst[PAD(base + 6 * m)] = cmul(y6, w6);
            dst[PAD(base + 7 * m)] = cmul(y7, w7);
        }
        __syncthreads();
        float2* tmp = src; src = dst; dst = tmp;
    }

    // final radix-2 stage: m = 4096, twiddle = 1
    #pragma unroll
    for (int i = 0; i < 8; i++) {
        const int t = tid + i * THREADS;            // t in [0, 4096)
        const float2 c0 = src[PAD(t)];
        const float2 c1 = src[PAD(t + 4096)];
        dst[PAD(t)]        = cadd(c0, c1);
        dst[PAD(t + 4096)] = csub(c0, c1);
    }
    __syncthreads();
}

__global__ void __launch_bounds__(THREADS, 1)
batch_align_kernel(const float* __restrict__ x,
                   const float* __restrict__ xref,
                   float* __restrict__ out_aligned,
                   float* __restrict__ out_inds) {
    const int row = blockIdx.x;
    const float* xr = x    + (size_t)row * FFT_N;
    const float* yr = xref + (size_t)row * FFT_N;

    extern __shared__ float smem_raw[];
    float2* b0   = (float2*)smem_raw;            // PADN float2
    float2* b1   = b0 + PADN;
    float*  redv = (float*)(b1 + PADN);
    int*    redi = (int*)(redv + THREADS);

    const int tid = threadIdx.x;

    // --- load z = x + i*xref ---
    #pragma unroll
    for (int i = 0; i < PTS_PER_T; i++) {
        const int k = tid + i * THREADS;
        b0[PAD(k)] = make_float2(xr[k], yr[k]);
    }
    __syncthreads();

    // --- forward FFT of packed signal: Z in b1 ---
    fft8192_r8(b0, b1, tid);

    // --- Hermitian split + V[k] = X[k] * conj(Y[k]) (pos. scale dropped) ---
    for (int k = tid; k <= FFT_N / 2; k += THREADS) {
        const float2 Zk = b1[PAD(k)];
        const float2 Zn = b1[PAD((FFT_N - k) & (FFT_N - 1))];
        const float Xr = Zk.x + Zn.x;
        const float Xi = Zk.y - Zn.y;
        const float Yr = Zk.y + Zn.y;
        const float Yi = Zn.x - Zk.x;
        const float Vr = Xr * Yr + Xi * Yi;
        const float Vi = Xi * Yr - Xr * Yi;
        b0[PAD(k)] = make_float2(Vr, Vi);
        if (k > 0 && k < FFT_N / 2)
            b0[PAD(FFT_N - k)] = make_float2(Vr, -Vi);
    }
    __syncthreads();

    // --- second forward FFT: corr (unscaled) = Re(b1[n]) ---
    fft8192_r8(b0, b1, tid);

    // --- argmax with first-index tiebreak ---
    float best = -INFINITY;
    int   bidx = 0;
    #pragma unroll
    for (int i = 0; i < PTS_PER_T; i++) {
        const int k = tid + i * THREADS;
        const float v = b1[PAD(k)].x;
        if (v > best) { best = v; bidx = k; }
    }
    redv[tid] = best;
    redi[tid] = bidx;
    __syncthreads();
    #pragma unroll 1
    for (int s = THREADS / 2; s > 0; s >>= 1) {
        if (tid < s) {
            const float v2 = redv[tid + s];
            const int   i2 = redi[tid + s];
            if (v2 > redv[tid] || (v2 == redv[tid] && i2 < redi[tid])) {
                redv[tid] = v2;
                redi[tid] = i2;
            }
        }
        __syncthreads();
    }
    const int ind = redi[0];

    // --- circular roll: out[k] = x[(k - ind) mod N] ---
    #pragma unroll
    for (int i = 0; i < PTS_PER_T; i++) {
        const int k = tid + i * THREADS;
        out_aligned[(size_t)row * FFT_N + k] = xr[(k - ind) & (FFT_N - 1)];
    }
    if (tid == 0)
        out_inds[row] = (float)ind;
}

extern "C" void kernel_launch(void* const* d_in, const int* in_sizes, int n_in,
                              void* d_out, int out_size) {
    const float* x    = (const float*)d_in[0];
    const float* xref = (const float*)d_in[1];
    float* out = (float*)d_out;

    const int rows = in_sizes[0] / FFT_N;    // 2048
    float* out_aligned = out;
    float* out_inds    = out + (size_t)rows * FFT_N;

    const size_t smem = 2 * PADN * sizeof(float2)
                      + THREADS * (sizeof(float) + sizeof(int));
    cudaFuncSetAttribute(batch_align_kernel,
                         cudaFuncAttributeMaxDynamicSharedMemorySize, (int)smem);
    batch_align_kernel<<<rows, THREADS, smem>>>(x, xref, out_aligned, out_inds);
}

// round 5
// speedup vs baseline: 3.0234x; 1.7230x over previous
#include <cuda_runtime.h>
#include <math.h>

#define FFT_N    8192
#define HALF_N   4096
#define THREADS  512
#define PAD(i)   ((i) + ((i) >> 4))
#define PADN     (FFT_N + (FFT_N >> 4))      // 8704 float2

__device__ constexpr int SLOT[16] = {0,4,8,12, 1,5,9,13, 2,6,10,14, 3,7,11,15};

__device__ __forceinline__ float2 cadd(float2 a, float2 b){ return make_float2(a.x+b.x, a.y+b.y); }
__device__ __forceinline__ float2 csub(float2 a, float2 b){ return make_float2(a.x-b.x, a.y-b.y); }
__device__ __forceinline__ float2 cmul(float2 a, float2 b){
    return make_float2(a.x*b.x - a.y*b.y, a.x*b.y + a.y*b.x);
}
__device__ __forceinline__ float2 cmul_negi(float2 a){ return make_float2(a.y, -a.x); }

// In-place 16-point DFT (e^-). Input a[n] natural order; output y[q] at a[SLOT[q]].
__device__ __forceinline__ void bfly16(float2 a[16]) {
    const float C  = 0.70710678118654752f;
    const float c8 = 0.92387953251128676f;
    const float s8 = 0.38268343236508977f;
    #pragma unroll
    for (int n0 = 0; n0 < 4; n0++) {
        float2 p0 = a[n0], p1 = a[n0+4], p2 = a[n0+8], p3 = a[n0+12];
        float2 t0 = cadd(p0,p2), t1 = csub(p0,p2);
        float2 t2 = cadd(p1,p3);
        float2 t3 = cmul_negi(csub(p1,p3));
        a[n0]    = cadd(t0,t2);
        a[n0+4]  = cadd(t1,t3);
        a[n0+8]  = csub(t0,t2);
        a[n0+12] = csub(t1,t3);
    }
    // w16^{n0*k0} at slot 4*k0+n0
    { float2 v=a[5];  a[5]  = make_float2( c8*v.x + s8*v.y,  c8*v.y - s8*v.x); }
    { float2 v=a[6];  a[6]  = make_float2( C*(v.x+v.y),      C*(v.y-v.x)); }
    { float2 v=a[7];  a[7]  = make_float2( s8*v.x + c8*v.y,  s8*v.y - c8*v.x); }
    { float2 v=a[9];  a[9]  = make_float2( C*(v.x+v.y),      C*(v.y-v.x)); }
    { float2 v=a[10]; a[10] = make_float2( v.y, -v.x); }
    { float2 v=a[11]; a[11] = make_float2( C*(v.y-v.x),     -C*(v.x+v.y)); }
    { float2 v=a[13]; a[13] = make_float2( s8*v.x + c8*v.y,  s8*v.y - c8*v.x); }
    { float2 v=a[14]; a[14] = make_float2( C*(v.y-v.x),     -C*(v.x+v.y)); }
    { float2 v=a[15]; a[15] = make_float2(-c8*v.x - s8*v.y,  s8*v.x - c8*v.y); }
    #pragma unroll
    for (int k0 = 0; k0 < 4; k0++) {
        float2 p0 = a[4*k0], p1 = a[4*k0+1], p2 = a[4*k0+2], p3 = a[4*k0+3];
        float2 t0 = cadd(p0,p2), t1 = csub(p0,p2);
        float2 t2 = cadd(p1,p3);
        float2 t3 = cmul_negi(csub(p1,p3));
        a[4*k0]   = cadd(t0,t2);
        a[4*k0+1] = cadd(t1,t3);
        a[4*k0+2] = csub(t0,t2);
        a[4*k0+3] = csub(t1,t3);
    }
}

// Apply stage twiddles w^q (w = e^{i*theta_step*jm}) in place.
__device__ __forceinline__ void stage_twiddle(float2 a[16], int jm, float theta_step) {
    float sn, cs;
    __sincosf(theta_step * (float)jm, &sn, &cs);
    float2 w1 = make_float2(cs, sn);
    float2 wq = w1;
    #pragma unroll
    for (int q = 1; q < 16; q++) {
        a[SLOT[q]] = cmul(a[SLOT[q]], wq);
        wq = cmul(wq, w1);
    }
}

template<int SH>
__device__ __forceinline__ void store16(float2* sb, int t, float2 a[16]) {
    const int m = 1 << SH;
    const int base = ((t & ~(m-1)) << 4) + (t & (m-1));
    #pragma unroll
    for (int q = 0; q < 16; q++)
        sb[PAD(base + q*m)] = a[SLOT[q]];
}

template<int SH, int STRIDE>
__device__ __forceinline__ void load_bfly_tw(const float2* sb, int t, float theta_step, float2 a[16]) {
    #pragma unroll
    for (int q = 0; q < 16; q++) a[q] = sb[PAD(t + q*STRIDE)];
    bfly16(a);
    stage_twiddle(a, t & ~((1<<SH)-1), theta_step);
}

__global__ void __launch_bounds__(THREADS, 2)
batch_align_kernel(const float* __restrict__ x,
                   const float* __restrict__ xref,
                   float* __restrict__ out_aligned,
                   float* __restrict__ out_inds) {
    const int row = blockIdx.x;
    const int tid = threadIdx.x;
    const float* xr = x    + (size_t)row * FFT_N;
    const float* yr = xref + (size_t)row * FFT_N;

    extern __shared__ float smem_raw[];
    float2* sb = (float2*)smem_raw;              // PADN float2
    float*  wv = (float*)(sb + PADN);            // 16
    int*    wi = (int*)(wv + 16);                // 16
    int*    fnd = (int*)(wi + 16);               // 1

    const float TH1 = -2.0f * (float)M_PI / (float)FFT_N;
    const float TH2 = -2.0f * (float)M_PI / (float)HALF_N;

    // ---------- FFT1 (N=8192), radices [16,16,16] + fused radix-2 ----------
    // pass 0: global -> regs -> smem (no smem read)
    {
        float2 a[16];
        #pragma unroll
        for (int q = 0; q < 16; q++) {
            const int k = tid + q * 512;
            a[q] = make_float2(xr[k], yr[k]);
        }
        bfly16(a);
        stage_twiddle(a, tid, TH1);
        store16<0>(sb, tid, a);
    }
    __syncthreads();
    // pass 1
    {
        float2 a[16];
        load_bfly_tw<4, 512>(sb, tid, TH1, a);
        __syncthreads();
        store16<4>(sb, tid, a);
    }
    __syncthreads();
    // pass 2
    {
        float2 a[16];
        load_bfly_tw<8, 512>(sb, tid, TH1, a);
        __syncthreads();
        store16<8>(sb, tid, a);
    }
    __syncthreads();

    // ---------- A1: fused final radix-2 (twiddle-free): Z in place ----------
    #pragma unroll
    for (int i = 0; i < 8; i++) {
        const int t2 = tid + i * 512;
        const float2 lo = sb[PAD(t2)];
        const float2 hi = sb[PAD(t2 + HALF_N)];
        sb[PAD(t2)]          = cadd(lo, hi);
        sb[PAD(t2 + HALF_N)] = csub(lo, hi);
    }
    __syncthreads();

    // ---------- A2: Hermitian split -> V[k] = X[k]*conj(Y[k]) (scale 4) ----------
    for (int k = tid; k <= HALF_N; k += THREADS) {
        const float2 Zk = sb[PAD(k)];
        const float2 Zn = sb[PAD((FFT_N - k) & (FFT_N - 1))];
        const float Xr = Zk.x + Zn.x;
        const float Xi = Zk.y - Zn.y;
        const float Yr = Zk.y + Zn.y;
        const float Yi = Zn.x - Zk.x;
        const float Vr = Xr * Yr + Xi * Yi;
        const float Vi = Xi * Yr - Xr * Yi;
        sb[PAD(k)] = make_float2(Vr, Vi);
        if (k > 0 && k < HALF_N)
            sb[PAD(FFT_N - k)] = make_float2(Vr, -Vi);
    }
    __syncthreads();

    // ---------- A3: Q[m] = (V[m]+V[m+M]) + i*e^{-2pi i m/N}(V[m]-V[m+M]) ----------
    #pragma unroll
    for (int i = 0; i < 8; i++) {
        const int m_ = tid + i * 512;
        const float2 Vm = sb[PAD(m_)];
        const float2 Vh = sb[PAD(m_ + HALF_N)];
        const float2 P = cadd(Vm, Vh);
        const float2 D = csub(Vm, Vh);
        float sn, cs;
        __sincosf(TH1 * (float)m_, &sn, &cs);
        const float2 R = make_float2(D.x * cs - D.y * sn, D.x * sn + D.y * cs);
        sb[PAD(m_)] = make_float2(P.x - R.y, P.y + R.x);   // P + i*R
    }
    __syncthreads();

    // ---------- FFT2 (N=4096 = 16^3) on Q; corr[2n]=Re F[n], corr[2n+1]=Im F[n] ----------
    const bool act = (tid < 256);
    // pass 0
    {
        float2 a[16];
        if (act) load_bfly_tw<0, 256>(sb, tid, TH2, a);
        __syncthreads();
        if (act) store16<0>(sb, tid, a);
    }
    __syncthreads();
    // pass 1
    {
        float2 a[16];
        if (act) load_bfly_tw<4, 256>(sb, tid, TH2, a);
        __syncthreads();
        if (act) store16<4>(sb, tid, a);
    }
    __syncthreads();

    // pass 2 (sh=8): jm = 0 for t<256 -> twiddles all 1; no store, argmax from regs
    float best = -INFINITY;
    int   bidx = 0x7fffffff;
    {
        float2 a[16];
        if (act) {
            #pragma unroll
            for (int q = 0; q < 16; q++) a[q] = sb[PAD(tid + q * 256)];
            bfly16(a);
            #pragma unroll
            for (int q = 0; q < 16; q++) {
                const int n = tid + q * 256;        // ascending in q
                const float2 v = a[SLOT[q]];
                if (v.x > best) { best = v.x; bidx = 2 * n; }
                if (v.y > best) { best = v.y; bidx = 2 * n + 1; }
            }
        }
    }

    // ---------- argmax reduction (index-aware, first-index tiebreak) ----------
    const int lane = tid & 31, wid = tid >> 5;
    #pragma unroll
    for (int off = 16; off > 0; off >>= 1) {
        const float v2 = __shfl_down_sync(0xffffffffu, best, off);
        const int   i2 = __shfl_down_sync(0xffffffffu, bidx, off);
        if (v2 > best || (v2 == best && i2 < bidx)) { best = v2; bidx = i2; }
    }
    if (lane == 0) { wv[wid] = best; wi[wid] = bidx; }
    __syncthreads();
    if (wid == 0) {
        float b2 = (lane < 16) ? wv[lane] : -INFINITY;
        int   j2 = (lane < 16) ? wi[lane] : 0x7fffffff;
        #pragma unroll
        for (int off = 8; off > 0; off >>= 1) {
            const float v2 = __shfl_down_sync(0xffffffffu, b2, off);
            const int   i2 = __shfl_down_sync(0xffffffffu, j2, off);
            if (v2 > b2 || (v2 == b2 && i2 < j2)) { b2 = v2; j2 = i2; }
        }
        if (lane == 0) *fnd = j2;
    }
    __syncthreads();
    const int ind = *fnd;

    // ---------- circular roll ----------
    #pragma unroll
    for (int i = 0; i < 16; i++) {
        const int k = tid + i * 512;
        out_aligned[(size_t)row * FFT_N + k] = xr[(k - ind) & (FFT_N - 1)];
    }
    if (tid == 0)
        out_inds[row] = (float)ind;
}

extern "C" void kernel_launch(void* const* d_in, const int* in_sizes, int n_in,
                              void* d_out, int out_size) {
    const float* x    = (const float*)d_in[0];
    const float* xref = (const float*)d_in[1];
    float* out = (float*)d_out;

    const int rows = in_sizes[0] / FFT_N;    // 2048
    float* out_aligned = out;
    float* out_inds    = out + (size_t)rows * FFT_N;

    const size_t smem = PADN * sizeof(float2) + 256;
    cudaFuncSetAttribute(batch_align_kernel,
                         cudaFuncAttributeMaxDynamicSharedMemorySize, (int)smem);
    batch_align_kernel<<<rows, THREADS, smem>>>(x, xref, out_aligned, out_inds);
}